// round 13
// baseline (speedup 1.0000x reference)
#include <cuda_runtime.h>
#include <math.h>

#define NN 4096
#define MM 8192
#define DD 512
#define N_ITERS 200
#define LOGA   (-8.317766166719343f)   // log(1/4096)
#define GRID 148
#define CHUNKS 64                       // for k_ot only
#define LN2F    0.69314718055994531f
#define LOG2EF  1.44269504088896340f

// ---------------- device scratch ----------------
__device__ __align__(16) unsigned short d_Cq[(size_t)NN * MM];  // u16 quantized cost (64MB)
__device__ __align__(16) float d_f[NN];      // f' (natural), for k_ot
__device__ __align__(16) float d_g[MM];      // g' (natural), for k_ot
__device__ __align__(16) float d_g2[MM];     // g'*log2e + fgC (staged fold)
__device__ __align__(16) float d_fSu[NN];    // initial f-fold seed (K2*qrmin)
__device__ __align__(16) float d_logb[MM];
__device__ __align__(16) float d_xsq[NN];
__device__ __align__(16) float d_ysq[MM];
__device__ __align__(16) unsigned d_qrmin[NN];
__device__ __align__(16) float d_ps[(size_t)GRID * MM];   // ~4.8 MB column partial sums
__device__ double d_ot;
__device__ double d_sq;
__device__ double d_cnt;
__device__ int    d_is64;
__device__ float d_qK2, d_fgC, d_step, d_invstep, d_qdqB;
__device__ unsigned d_barcnt;

__device__ __forceinline__ float ex2(float x) {
    float r; asm("ex2.approx.ftz.f32 %0, %1;" : "=f"(r) : "f"(x)); return r;
}
__device__ __forceinline__ float lg2(float x) {
    float r; asm("lg2.approx.ftz.f32 %0, %1;" : "=f"(r) : "f"(x)); return r;
}
// u16 -> float(2^23 + q), one PRMT
__device__ __forceinline__ float qf_lo(unsigned w) {
    return __uint_as_float(__byte_perm(w, 0x4B000000u, 0x7410));
}
__device__ __forceinline__ float qf_hi(unsigned w) {
    return __uint_as_float(__byte_perm(w, 0x4B000000u, 0x7432));
}

// monotonic-counter grid barrier (counter reset by k_ginit before each replay)
__device__ __forceinline__ void gridbar(int tid, unsigned target) {
    __syncthreads();
    if (tid == 0) {
        __threadfence();
        atomicAdd(&d_barcnt, 1u);
        while (*(volatile unsigned*)&d_barcnt < target) { __nanosleep(64); }
    }
    __syncthreads();
}

// ---------------- init ----------------
__global__ void k_init(const float* __restrict__ tgt, const int* __restrict__ al_raw) {
    __shared__ float red[32];
    __shared__ float s_total;
    int t = threadIdx.x;
    float s = 0.f;
    for (int j = t; j < MM; j += 1024) s += tgt[j];
    #pragma unroll
    for (int o = 16; o; o >>= 1) s += __shfl_down_sync(0xffffffffu, s, o);
    if ((t & 31) == 0) red[t >> 5] = s;
    __syncthreads();
    if (t < 32) {
        float v = red[t];
        #pragma unroll
        for (int o = 16; o; o >>= 1) v += __shfl_down_sync(0xffffffffu, v, o);
        if (t == 0) s_total = v;
    }
    __syncthreads();
    float lt = logf(s_total);
    for (int j = t; j < MM; j += 1024) d_logb[j] = logf(tgt[j]) - lt;
    for (int i = t; i < NN; i += 1024) d_qrmin[i] = 0xFFFFu;
    int odd_nz = 0;
    for (int i = t; i < NN / 2; i += 1024)
        if (al_raw[2 * i + 1] != 0) odd_nz = 1;
    odd_nz = __syncthreads_or(odd_nz);
    if (t == 0) {
        d_is64 = odd_nz ? 0 : 1;
        d_ot = 0.0; d_sq = 0.0; d_cnt = 0.0;
    }
}

// ---------------- row squared norms ----------------
__global__ __launch_bounds__(128) void k_sqnorm(const float* __restrict__ X, int which) {
    int row = blockIdx.x, t = threadIdx.x;
    float4 v = ((const float4*)X)[(size_t)row * (DD / 4) + t];
    float s = v.x * v.x + v.y * v.y + v.z * v.z + v.w * v.w;
    #pragma unroll
    for (int o = 16; o; o >>= 1) s += __shfl_down_sync(0xffffffffu, s, o);
    __shared__ float red[4];
    if ((t & 31) == 0) red[t >> 5] = s;
    __syncthreads();
    if (t == 0) {
        float tot = red[0] + red[1] + red[2] + red[3];
        if (which == 0) d_xsq[row] = tot; else d_ysq[row] = tot;
    }
}

// ---------------- quantizer constants from norm bounds (C in [0, B]) ----------------
__global__ void k_scale() {
    __shared__ float red[32];
    int t = threadIdx.x;
    float mx = 0.f;
    for (int i = t; i < NN; i += 1024) mx = fmaxf(mx, d_xsq[i]);
    #pragma unroll
    for (int o = 16; o; o >>= 1) mx = fmaxf(mx, __shfl_xor_sync(0xffffffffu, mx, o));
    if ((t & 31) == 0) red[t >> 5] = mx;
    __syncthreads();
    float my = 0.f;
    for (int i = t; i < MM; i += 1024) my = fmaxf(my, d_ysq[i]);
    #pragma unroll
    for (int o = 16; o; o >>= 1) my = fmaxf(my, __shfl_xor_sync(0xffffffffu, my, o));
    __shared__ float red2[32];
    if ((t & 31) == 0) red2[t >> 5] = my;
    __syncthreads();
    if (t == 0) {
        float MX = 0.f, MY = 0.f;
        #pragma unroll
        for (int k = 0; k < 32; k++) { MX = fmaxf(MX, red[k]); MY = fmaxf(MY, red2[k]); }
        double B = 1.02 * ((double)sqrtf(MX) + (double)sqrtf(MY)) + 1e-3;
        double st = B / 65535.0;
        const double L2E = 1.4426950408889634;
        float K2f = (float)(10.0 * st * L2E);
        d_step = (float)st;
        d_invstep = (float)(1.0 / st);
        d_qK2 = K2f;
        d_fgC = (float)(8388608.0 * (double)K2f);   // 2^23*K2 fold for magic dequant
        d_qdqB = (float)(-8388608.0 * st);
    }
}

// ---------------- GEMM (reg-prefetch double buffer) + cdist epilogue + row min ----------------
__global__ __launch_bounds__(256, 2) void k_gemm(const float* __restrict__ X, const float* __restrict__ Y) {
    __shared__ float As[16][128];
    __shared__ float Bs[16][128];
    __shared__ unsigned rmin[128];
    int tid = threadIdx.x;
    int bx = blockIdx.x, by = blockIdx.y;
    int tx = tid & 15, ty = tid >> 4;
    if (tid < 128) rmin[tid] = 0xFFFFu;
    float acc[8][8];
    #pragma unroll
    for (int i = 0; i < 8; i++)
        #pragma unroll
        for (int j = 0; j < 8; j++) acc[i][j] = 0.f;

    const float* Xb = X + (size_t)by * 128 * DD;
    const float* Yb = Y + (size_t)bx * 128 * DD;

    int l0 = tid, r0i = l0 >> 2, c40 = (l0 & 3) * 4;
    int l1 = tid + 256, r1i = l1 >> 2, c41 = (l1 & 3) * 4;

    float4 va[2], vb[2];
    va[0] = *(const float4*)(Xb + (size_t)r0i * DD + c40);
    va[1] = *(const float4*)(Xb + (size_t)r1i * DD + c41);
    vb[0] = *(const float4*)(Yb + (size_t)r0i * DD + c40);
    vb[1] = *(const float4*)(Yb + (size_t)r1i * DD + c41);

    for (int kt = 0; kt < DD; kt += 16) {
        __syncthreads();
        As[c40 + 0][r0i] = va[0].x; As[c40 + 1][r0i] = va[0].y;
        As[c40 + 2][r0i] = va[0].z; As[c40 + 3][r0i] = va[0].w;
        As[c41 + 0][r1i] = va[1].x; As[c41 + 1][r1i] = va[1].y;
        As[c41 + 2][r1i] = va[1].z; As[c41 + 3][r1i] = va[1].w;
        Bs[c40 + 0][r0i] = vb[0].x; Bs[c40 + 1][r0i] = vb[0].y;
        Bs[c40 + 2][r0i] = vb[0].z; Bs[c40 + 3][r0i] = vb[0].w;
        Bs[c41 + 0][r1i] = vb[1].x; Bs[c41 + 1][r1i] = vb[1].y;
        Bs[c41 + 2][r1i] = vb[1].z; Bs[c41 + 3][r1i] = vb[1].w;
        __syncthreads();
        if (kt + 16 < DD) {
            va[0] = *(const float4*)(Xb + (size_t)r0i * DD + kt + 16 + c40);
            va[1] = *(const float4*)(Xb + (size_t)r1i * DD + kt + 16 + c41);
            vb[0] = *(const float4*)(Yb + (size_t)r0i * DD + kt + 16 + c40);
            vb[1] = *(const float4*)(Yb + (size_t)r1i * DD + kt + 16 + c41);
        }
        #pragma unroll
        for (int kk = 0; kk < 16; kk++) {
            float a[8], b[8];
            *(float4*)(a)     = *(const float4*)&As[kk][ty * 8];
            *(float4*)(a + 4) = *(const float4*)&As[kk][ty * 8 + 4];
            *(float4*)(b)     = *(const float4*)&Bs[kk][tx * 8];
            *(float4*)(b + 4) = *(const float4*)&Bs[kk][tx * 8 + 4];
            #pragma unroll
            for (int i = 0; i < 8; i++)
                #pragma unroll
                for (int j = 0; j < 8; j++)
                    acc[i][j] = fmaf(a[i], b[j], acc[i][j]);
        }
    }
    int i0 = by * 128 + ty * 8;
    int j0 = bx * 128 + tx * 8;
    float inv = d_invstep;
    float ys[8];
    #pragma unroll
    for (int jj = 0; jj < 8; jj++) ys[jj] = d_ysq[j0 + jj];
    #pragma unroll
    for (int ii = 0; ii < 8; ii++) {
        float xs = d_xsq[i0 + ii];
        unsigned q[8];
        unsigned qm = 0xFFFFu;
        #pragma unroll
        for (int jj = 0; jj < 8; jj++) {
            float sq = xs + ys[jj] - 2.0f * acc[ii][jj];
            float c = sqrtf(fmaxf(sq, 1e-12f));
            unsigned qq = __float2uint_rn(c * inv);
            q[jj] = qq > 65535u ? 65535u : qq;
            qm = min(qm, q[jj]);
        }
        atomicMin(&rmin[ty * 8 + ii], qm);
        uint4 o;
        o.x = __byte_perm(q[0], q[1], 0x5410);
        o.y = __byte_perm(q[2], q[3], 0x5410);
        o.z = __byte_perm(q[4], q[5], 0x5410);
        o.w = __byte_perm(q[6], q[7], 0x5410);
        *(uint4*)(d_Cq + (size_t)(i0 + ii) * MM + j0) = o;
    }
    __syncthreads();
    if (tid < 128) atomicMin(&d_qrmin[by * 128 + tid], rmin[tid]);
}

// ---------------- staging init: g2=fgC, fSu seed, barrier reset ----------------
__global__ void k_ginit() {
    int j = blockIdx.x * 256 + threadIdx.x;
    d_g2[j] = d_fgC;
    if (j < NN) d_fSu[j] = d_qK2 * (float)d_qrmin[j];
    if (j == 0) d_barcnt = 0u;
}

// ---------------- PERSISTENT FUSED LOOP: one ex2/element, 1024 threads, 8 cols/thread ----------------
__global__ __launch_bounds__(1024, 1) void k_loop() {
    __shared__ float wsum0[32], wsum1[32];
    __shared__ float sc[2];           // c_r = 2^(fle_new - fle_prev) for tile rows
    __shared__ float sfp[32];         // per-row fold (fle of previous iter)
    int t = threadIdx.x, blk = blockIdx.x;
    int w = t >> 5, l = t & 31;
    float K2 = d_qK2, fgC = d_fgC;
    int r0 = (blk * NN) / GRID, r1 = ((blk + 1) * NN) / GRID;
    int nr = r1 - r0;                            // 27 or 28 rows
    int c0 = (blk * MM) / GRID, c1 = ((blk + 1) * MM) / GRID;
    const uint4* Cblk = (const uint4*)(d_Cq + (size_t)r0 * MM) + t;   // 8 cols/thread
    // gcomb: 16 threads/col, clamped so all lanes run the shfl (no partial-warp hang)
    int cIdx = c0 + (t >> 4);
    int colc = min(cIdx, MM - 1);
    bool cwrite = cIdx < c1;
    int sub = t & 15;
    unsigned bcnt = 0;

    if (t < nr) sfp[t] = d_fSu[r0 + t];
    __syncthreads();

    for (int it = 0; it < N_ITERS; it++) {
        bool last = (it == N_ITERS - 1);
        // this thread's 8 g2 values (cols t*8 .. t*8+7)
        float g2r[8];
        {
            float4 a = __ldcg(((const float4*)d_g2) + t * 2);
            float4 b = __ldcg(((const float4*)d_g2) + t * 2 + 1);
            g2r[0] = a.x; g2r[1] = a.y; g2r[2] = a.z; g2r[3] = a.w;
            g2r[4] = b.x; g2r[5] = b.y; g2r[6] = b.z; g2r[7] = b.w;
        }
        float acc[8];
        #pragma unroll
        for (int j = 0; j < 8; j++) acc[j] = 0.f;

        for (int ra = 0; ra < nr; ra += 2) {
            bool hasb = (ra + 1) < nr;
            int rb = hasb ? ra + 1 : ra;          // clamp: stay in-bounds
            float fp0 = sfp[ra];
            float fp1 = sfp[rb];
            uint4 cv0 = Cblk[(size_t)ra * 1024];
            uint4 cv1 = Cblk[(size_t)rb * 1024];
            float e0[8], e1[8];
            e0[0] = ex2(fmaf(qf_lo(cv0.x), -K2, g2r[0] + fp0));
            e0[1] = ex2(fmaf(qf_hi(cv0.x), -K2, g2r[1] + fp0));
            e0[2] = ex2(fmaf(qf_lo(cv0.y), -K2, g2r[2] + fp0));
            e0[3] = ex2(fmaf(qf_hi(cv0.y), -K2, g2r[3] + fp0));
            e0[4] = ex2(fmaf(qf_lo(cv0.z), -K2, g2r[4] + fp0));
            e0[5] = ex2(fmaf(qf_hi(cv0.z), -K2, g2r[5] + fp0));
            e0[6] = ex2(fmaf(qf_lo(cv0.w), -K2, g2r[6] + fp0));
            e0[7] = ex2(fmaf(qf_hi(cv0.w), -K2, g2r[7] + fp0));
            e1[0] = ex2(fmaf(qf_lo(cv1.x), -K2, g2r[0] + fp1));
            e1[1] = ex2(fmaf(qf_hi(cv1.x), -K2, g2r[1] + fp1));
            e1[2] = ex2(fmaf(qf_lo(cv1.y), -K2, g2r[2] + fp1));
            e1[3] = ex2(fmaf(qf_hi(cv1.y), -K2, g2r[3] + fp1));
            e1[4] = ex2(fmaf(qf_lo(cv1.z), -K2, g2r[4] + fp1));
            e1[5] = ex2(fmaf(qf_hi(cv1.z), -K2, g2r[5] + fp1));
            e1[6] = ex2(fmaf(qf_lo(cv1.w), -K2, g2r[6] + fp1));
            e1[7] = ex2(fmaf(qf_hi(cv1.w), -K2, g2r[7] + fp1));
            float p0 = ((e0[0] + e0[1]) + (e0[2] + e0[3]))
                     + ((e0[4] + e0[5]) + (e0[6] + e0[7]));
            float p1 = ((e1[0] + e1[1]) + (e1[2] + e1[3]))
                     + ((e1[4] + e1[5]) + (e1[6] + e1[7]));
            #pragma unroll
            for (int o = 16; o; o >>= 1) {
                p0 += __shfl_xor_sync(0xffffffffu, p0, o);
                p1 += __shfl_xor_sync(0xffffffffu, p1, o);
            }
            if (l == 0) { wsum0[w] = p0; wsum1[w] = p1; }
            __syncthreads();
            // finalize rows in parallel: warp 0 -> ra, warp 1 -> ra+1
            if (w == 0) {
                float S = wsum0[l];
                #pragma unroll
                for (int o = 16; o; o >>= 1) S += __shfl_xor_sync(0xffffffffu, S, o);
                if (l == 0) {
                    S = fmaxf(S, 1e-37f);
                    float lgS = lg2(S);
                    float fle = -12.0f - lgS + sfp[ra];   // log2(1/4096) = -12
                    sfp[ra] = fle;
                    sc[0] = ex2(-12.0f - lgS);            // 2^(fle - fp)
                    if (last) d_f[r0 + ra] = fle * LN2F;
                }
            } else if (w == 1 && hasb) {
                float S = wsum1[l];
                #pragma unroll
                for (int o = 16; o; o >>= 1) S += __shfl_xor_sync(0xffffffffu, S, o);
                if (l == 0) {
                    S = fmaxf(S, 1e-37f);
                    float lgS = lg2(S);
                    float fle = -12.0f - lgS + sfp[rb];
                    sfp[rb] = fle;
                    sc[1] = ex2(-12.0f - lgS);
                    if (last) d_f[r0 + rb] = fle * LN2F;
                }
            }
            __syncthreads();
            // fold exps into column accumulators (bounded: Σ e·c per row = 2^-12)
            float cA = sc[0];
            #pragma unroll
            for (int j = 0; j < 8; j++) acc[j] = fmaf(e0[j], cA, acc[j]);
            if (hasb) {
                float cB = sc[1];
                #pragma unroll
                for (int j = 0; j < 8; j++) acc[j] = fmaf(e1[j], cB, acc[j]);
            }
        }

        // partial_j = acc_j * 2^(fgC - g2_j)
        {
            float* dst = d_ps + (size_t)blk * MM + (size_t)t * 8;
            float4 oa, ob;
            oa.x = acc[0] * ex2(fgC - g2r[0]);
            oa.y = acc[1] * ex2(fgC - g2r[1]);
            oa.z = acc[2] * ex2(fgC - g2r[2]);
            oa.w = acc[3] * ex2(fgC - g2r[3]);
            ob.x = acc[4] * ex2(fgC - g2r[4]);
            ob.y = acc[5] * ex2(fgC - g2r[5]);
            ob.z = acc[6] * ex2(fgC - g2r[6]);
            ob.w = acc[7] * ex2(fgC - g2r[7]);
            *(float4*)(dst)     = oa;
            *(float4*)(dst + 4) = ob;
        }
        bcnt += GRID;
        gridbar(t, bcnt);

        // gcomb: block owns cols [c0, c1), 16 threads per column
        {
            float V = 0.f;
            #pragma unroll 5
            for (int k = sub; k < GRID; k += 16)
                V += __ldcg(&d_ps[(size_t)k * MM + colc]);
            #pragma unroll
            for (int o = 8; o; o >>= 1) V += __shfl_xor_sync(0xffffffffu, V, o, 16);
            if (sub == 0 && cwrite) {
                V = fmaxf(V, 1e-37f);
                float g = d_logb[colc] - LN2F * lg2(V);
                d_g2[colc] = fmaf(g, LOG2EF, fgC);
                if (last) d_g[colc] = g;
            }
        }
        bcnt += GRID;
        gridbar(t, bcnt);
    }
}

// ---------------- final OT loss ----------------
__global__ __launch_bounds__(256) void k_ot() {
    int t = threadIdx.x;
    int j = blockIdx.x * 1024 + t * 4;
    int r0 = blockIdx.y * (NN / CHUNKS);
    float K2 = d_qK2, stepf = d_step, qB = d_qdqB, fgC = d_fgC;
    float4 gv = *(const float4*)(d_g + j);
    float base[4];
    base[0] = fmaf(gv.x, LOG2EF, fgC);
    base[1] = fmaf(gv.y, LOG2EF, fgC);
    base[2] = fmaf(gv.z, LOG2EF, fgC);
    base[3] = fmaf(gv.w, LOG2EF, fgC);
    const unsigned short* Cb = d_Cq + j;
    float acc = 0.f;
    for (int r = r0; r < r0 + (NN / CHUNKS); r++) {
        float frl2 = __ldg(&d_f[r]) * LOG2EF;
        uint2 v = *(const uint2*)(Cb + (size_t)r * MM);
        float qf[4] = {qf_lo(v.x), qf_hi(v.x), qf_lo(v.y), qf_hi(v.y)};
        #pragma unroll
        for (int c = 0; c < 4; c++) {
            float p = ex2(fmaf(qf[c], -K2, base[c] + frl2));
            float cd = fmaf(qf[c], stepf, qB);
            acc = fmaf(p, cd, acc);
        }
    }
    double da = (double)acc;
    #pragma unroll
    for (int o = 16; o; o >>= 1) da += __shfl_down_sync(0xffffffffu, da, o);
    __shared__ double sd[8];
    int lane = t & 31, w = t >> 5;
    if (lane == 0) sd[w] = da;
    __syncthreads();
    if (t == 0) {
        double tot = 0.0;
        #pragma unroll
        for (int k = 0; k < 8; k++) tot += sd[k];
        atomicAdd(&d_ot, tot);
    }
}

// ---------------- supervised alignment MSE ----------------
__global__ __launch_bounds__(128) void k_dist(const float* __restrict__ X,
                                              const float* __restrict__ W,
                                              const int* __restrict__ al) {
    int row = blockIdx.x, t = threadIdx.x;
    long long idx; int mask;
    if (d_is64) {
        long long v = ((const long long*)al)[row];
        mask = (v != -1LL);
        idx = v < 0 ? 0 : v;
    } else {
        int v = al[row];
        mask = (v != -1);
        idx = v < 0 ? 0 : (long long)v;
    }
    float4 a = ((const float4*)X)[(size_t)row * (DD / 4) + t];
    float4 b = ((const float4*)W)[(size_t)idx * (DD / 4) + t];
    float dx = a.x - b.x, dy = a.y - b.y, dz = a.z - b.z, dw = a.w - b.w;
    float s = dx * dx + dy * dy + dz * dz + dw * dw;
    #pragma unroll
    for (int o = 16; o; o >>= 1) s += __shfl_down_sync(0xffffffffu, s, o);
    __shared__ float red[4];
    if ((t & 31) == 0) red[t >> 5] = s;
    __syncthreads();
    if (t == 0) {
        float tot = red[0] + red[1] + red[2] + red[3];
        if (mask) {
            atomicAdd(&d_sq, (double)tot);
            atomicAdd(&d_cnt, 1.0);
        }
    }
}

// ---------------- finalize ----------------
__global__ void k_final(float* out) {
    double dl = (d_cnt > 0.0) ? d_sq / (d_cnt * (double)DD) : 0.0;
    out[0] = (float)(d_ot + dl);
}

// ---------------- launch ----------------
extern "C" void kernel_launch(void* const* d_in, const int* in_sizes, int n_in,
                              void* d_out, int out_size) {
    const float* X  = (const float*)d_in[0];
    const float* W  = (const float*)d_in[1];
    const int*   AL = (const int*)d_in[2];
    const float* T  = (const float*)d_in[3];
    float* out = (float*)d_out;

    k_init<<<1, 1024>>>(T, AL);
    k_sqnorm<<<NN, 128>>>(X, 0);
    k_sqnorm<<<MM, 128>>>(W, 1);
    k_scale<<<1, 1024>>>();
    dim3 gg(MM / 128, NN / 128);
    k_gemm<<<gg, 256>>>(X, W);
    k_ginit<<<MM / 256, 256>>>();

    k_loop<<<GRID, 1024>>>();

    k_ot<<<dim3(8, CHUNKS), 256>>>();
    k_dist<<<NN, 128>>>(X, W, AL);
    k_final<<<1, 1>>>(out);
}

// round 14
// speedup vs baseline: 1.1454x; 1.1454x over previous
#include <cuda_runtime.h>
#include <math.h>

#define NN 4096
#define MM 8192
#define DD 512
#define N_ITERS 200
#define LOGA   (-8.317766166719343f)   // log(1/4096)
#define GRID 148
#define CHUNKS 64                       // for k_ot only
#define LN2F    0.69314718055994531f
#define LOG2EF  1.44269504088896340f

// ---------------- device scratch ----------------
__device__ __align__(16) unsigned short d_Cq[(size_t)NN * MM];  // u16 quantized cost (64MB)
__device__ __align__(16) float d_f[NN];      // f' (natural), for k_ot
__device__ __align__(16) float d_g[MM];      // g' (natural), for k_ot
__device__ __align__(16) float d_g2[MM];     // g'*log2e + fgC (staged fold)
__device__ __align__(16) float d_fSu[NN];    // initial f-fold seed (K2*qrmin)
__device__ __align__(16) float d_logb[MM];
__device__ __align__(16) float d_xsq[NN];
__device__ __align__(16) float d_ysq[MM];
__device__ __align__(16) unsigned d_qrmin[NN];
__device__ __align__(16) float d_ps[(size_t)GRID * MM];   // ~4.8 MB column partial sums
__device__ double d_ot;
__device__ double d_sq;
__device__ double d_cnt;
__device__ int    d_is64;
__device__ float d_qK2, d_fgC, d_step, d_invstep, d_qdqB;
__device__ unsigned d_barcnt;

__device__ __forceinline__ float ex2(float x) {
    float r; asm("ex2.approx.ftz.f32 %0, %1;" : "=f"(r) : "f"(x)); return r;
}
__device__ __forceinline__ float lg2(float x) {
    float r; asm("lg2.approx.ftz.f32 %0, %1;" : "=f"(r) : "f"(x)); return r;
}
// u16 -> float(2^23 + q), one PRMT
__device__ __forceinline__ float qf_lo(unsigned w) {
    return __uint_as_float(__byte_perm(w, 0x4B000000u, 0x7410));
}
__device__ __forceinline__ float qf_hi(unsigned w) {
    return __uint_as_float(__byte_perm(w, 0x4B000000u, 0x7432));
}

// monotonic-counter grid barrier (counter reset by k_ginit before each replay)
__device__ __forceinline__ void gridbar(int tid, unsigned target) {
    __syncthreads();
    if (tid == 0) {
        __threadfence();
        atomicAdd(&d_barcnt, 1u);
        while (*(volatile unsigned*)&d_barcnt < target) { __nanosleep(64); }
    }
    __syncthreads();
}

// ---------------- init ----------------
__global__ void k_init(const float* __restrict__ tgt, const int* __restrict__ al_raw) {
    __shared__ float red[32];
    __shared__ float s_total;
    int t = threadIdx.x;
    float s = 0.f;
    for (int j = t; j < MM; j += 1024) s += tgt[j];
    #pragma unroll
    for (int o = 16; o; o >>= 1) s += __shfl_down_sync(0xffffffffu, s, o);
    if ((t & 31) == 0) red[t >> 5] = s;
    __syncthreads();
    if (t < 32) {
        float v = red[t];
        #pragma unroll
        for (int o = 16; o; o >>= 1) v += __shfl_down_sync(0xffffffffu, v, o);
        if (t == 0) s_total = v;
    }
    __syncthreads();
    float lt = logf(s_total);
    for (int j = t; j < MM; j += 1024) d_logb[j] = logf(tgt[j]) - lt;
    for (int i = t; i < NN; i += 1024) d_qrmin[i] = 0xFFFFu;
    int odd_nz = 0;
    for (int i = t; i < NN / 2; i += 1024)
        if (al_raw[2 * i + 1] != 0) odd_nz = 1;
    odd_nz = __syncthreads_or(odd_nz);
    if (t == 0) {
        d_is64 = odd_nz ? 0 : 1;
        d_ot = 0.0; d_sq = 0.0; d_cnt = 0.0;
    }
}

// ---------------- row squared norms ----------------
__global__ __launch_bounds__(128) void k_sqnorm(const float* __restrict__ X, int which) {
    int row = blockIdx.x, t = threadIdx.x;
    float4 v = ((const float4*)X)[(size_t)row * (DD / 4) + t];
    float s = v.x * v.x + v.y * v.y + v.z * v.z + v.w * v.w;
    #pragma unroll
    for (int o = 16; o; o >>= 1) s += __shfl_down_sync(0xffffffffu, s, o);
    __shared__ float red[4];
    if ((t & 31) == 0) red[t >> 5] = s;
    __syncthreads();
    if (t == 0) {
        float tot = red[0] + red[1] + red[2] + red[3];
        if (which == 0) d_xsq[row] = tot; else d_ysq[row] = tot;
    }
}

// ---------------- quantizer constants from norm bounds (C in [0, B]) ----------------
__global__ void k_scale() {
    __shared__ float red[32];
    int t = threadIdx.x;
    float mx = 0.f;
    for (int i = t; i < NN; i += 1024) mx = fmaxf(mx, d_xsq[i]);
    #pragma unroll
    for (int o = 16; o; o >>= 1) mx = fmaxf(mx, __shfl_xor_sync(0xffffffffu, mx, o));
    if ((t & 31) == 0) red[t >> 5] = mx;
    __syncthreads();
    float my = 0.f;
    for (int i = t; i < MM; i += 1024) my = fmaxf(my, d_ysq[i]);
    #pragma unroll
    for (int o = 16; o; o >>= 1) my = fmaxf(my, __shfl_xor_sync(0xffffffffu, my, o));
    __shared__ float red2[32];
    if ((t & 31) == 0) red2[t >> 5] = my;
    __syncthreads();
    if (t == 0) {
        float MX = 0.f, MY = 0.f;
        #pragma unroll
        for (int k = 0; k < 32; k++) { MX = fmaxf(MX, red[k]); MY = fmaxf(MY, red2[k]); }
        double B = 1.02 * ((double)sqrtf(MX) + (double)sqrtf(MY)) + 1e-3;
        double st = B / 65535.0;
        const double L2E = 1.4426950408889634;
        float K2f = (float)(10.0 * st * L2E);
        d_step = (float)st;
        d_invstep = (float)(1.0 / st);
        d_qK2 = K2f;
        d_fgC = (float)(8388608.0 * (double)K2f);   // 2^23*K2 fold for magic dequant
        d_qdqB = (float)(-8388608.0 * st);
    }
}

// ---------------- GEMM (reg-prefetch double buffer) + cdist epilogue + row min ----------------
__global__ __launch_bounds__(256, 2) void k_gemm(const float* __restrict__ X, const float* __restrict__ Y) {
    __shared__ float As[16][128];
    __shared__ float Bs[16][128];
    __shared__ unsigned rmin[128];
    int tid = threadIdx.x;
    int bx = blockIdx.x, by = blockIdx.y;
    int tx = tid & 15, ty = tid >> 4;
    if (tid < 128) rmin[tid] = 0xFFFFu;
    float acc[8][8];
    #pragma unroll
    for (int i = 0; i < 8; i++)
        #pragma unroll
        for (int j = 0; j < 8; j++) acc[i][j] = 0.f;

    const float* Xb = X + (size_t)by * 128 * DD;
    const float* Yb = Y + (size_t)bx * 128 * DD;

    int l0 = tid, r0i = l0 >> 2, c40 = (l0 & 3) * 4;
    int l1 = tid + 256, r1i = l1 >> 2, c41 = (l1 & 3) * 4;

    float4 va[2], vb[2];
    va[0] = *(const float4*)(Xb + (size_t)r0i * DD + c40);
    va[1] = *(const float4*)(Xb + (size_t)r1i * DD + c41);
    vb[0] = *(const float4*)(Yb + (size_t)r0i * DD + c40);
    vb[1] = *(const float4*)(Yb + (size_t)r1i * DD + c41);

    for (int kt = 0; kt < DD; kt += 16) {
        __syncthreads();
        As[c40 + 0][r0i] = va[0].x; As[c40 + 1][r0i] = va[0].y;
        As[c40 + 2][r0i] = va[0].z; As[c40 + 3][r0i] = va[0].w;
        As[c41 + 0][r1i] = va[1].x; As[c41 + 1][r1i] = va[1].y;
        As[c41 + 2][r1i] = va[1].z; As[c41 + 3][r1i] = va[1].w;
        Bs[c40 + 0][r0i] = vb[0].x; Bs[c40 + 1][r0i] = vb[0].y;
        Bs[c40 + 2][r0i] = vb[0].z; Bs[c40 + 3][r0i] = vb[0].w;
        Bs[c41 + 0][r1i] = vb[1].x; Bs[c41 + 1][r1i] = vb[1].y;
        Bs[c41 + 2][r1i] = vb[1].z; Bs[c41 + 3][r1i] = vb[1].w;
        __syncthreads();
        if (kt + 16 < DD) {
            va[0] = *(const float4*)(Xb + (size_t)r0i * DD + kt + 16 + c40);
            va[1] = *(const float4*)(Xb + (size_t)r1i * DD + kt + 16 + c41);
            vb[0] = *(const float4*)(Yb + (size_t)r0i * DD + kt + 16 + c40);
            vb[1] = *(const float4*)(Yb + (size_t)r1i * DD + kt + 16 + c41);
        }
        #pragma unroll
        for (int kk = 0; kk < 16; kk++) {
            float a[8], b[8];
            *(float4*)(a)     = *(const float4*)&As[kk][ty * 8];
            *(float4*)(a + 4) = *(const float4*)&As[kk][ty * 8 + 4];
            *(float4*)(b)     = *(const float4*)&Bs[kk][tx * 8];
            *(float4*)(b + 4) = *(const float4*)&Bs[kk][tx * 8 + 4];
            #pragma unroll
            for (int i = 0; i < 8; i++)
                #pragma unroll
                for (int j = 0; j < 8; j++)
                    acc[i][j] = fmaf(a[i], b[j], acc[i][j]);
        }
    }
    int i0 = by * 128 + ty * 8;
    int j0 = bx * 128 + tx * 8;
    float inv = d_invstep;
    float ys[8];
    #pragma unroll
    for (int jj = 0; jj < 8; jj++) ys[jj] = d_ysq[j0 + jj];
    #pragma unroll
    for (int ii = 0; ii < 8; ii++) {
        float xs = d_xsq[i0 + ii];
        unsigned q[8];
        unsigned qm = 0xFFFFu;
        #pragma unroll
        for (int jj = 0; jj < 8; jj++) {
            float sq = xs + ys[jj] - 2.0f * acc[ii][jj];
            float c = sqrtf(fmaxf(sq, 1e-12f));
            unsigned qq = __float2uint_rn(c * inv);
            q[jj] = qq > 65535u ? 65535u : qq;
            qm = min(qm, q[jj]);
        }
        atomicMin(&rmin[ty * 8 + ii], qm);
        uint4 o;
        o.x = __byte_perm(q[0], q[1], 0x5410);
        o.y = __byte_perm(q[2], q[3], 0x5410);
        o.z = __byte_perm(q[4], q[5], 0x5410);
        o.w = __byte_perm(q[6], q[7], 0x5410);
        *(uint4*)(d_Cq + (size_t)(i0 + ii) * MM + j0) = o;
    }
    __syncthreads();
    if (tid < 128) atomicMin(&d_qrmin[by * 128 + tid], rmin[tid]);
}

// ---------------- staging init: g2=fgC, fSu seed, barrier reset ----------------
__global__ void k_ginit() {
    int j = blockIdx.x * 256 + threadIdx.x;
    d_g2[j] = d_fgC;
    if (j < NN) d_fSu[j] = d_qK2 * (float)d_qrmin[j];
    if (j == 0) d_barcnt = 0u;
}

// ---------------- PERSISTENT LOOP (R10 structure, conflict-free f-pass) ----------------
__global__ __launch_bounds__(1024, 1) void k_loop() {
    __shared__ float sg[MM];       // staged g2 (32 KB)
    __shared__ float sf[32];       // this block's f-fold (fle + fgC)
    int t = threadIdx.x, blk = blockIdx.x;
    int w = t >> 5, l = t & 31;
    float K2 = d_qK2, fgC = d_fgC;
    int r0 = (blk * NN) / GRID, r1 = ((blk + 1) * NN) / GRID;
    int nr = r1 - r0;                            // 27 or 28 rows
    int c0 = (blk * MM) / GRID, c1 = ((blk + 1) * MM) / GRID;
    int row = r0 + w;
    bool factive = (w < nr);                     // warp-uniform guard (safe w/ shfl)
    const unsigned short* Crow16 = d_Cq + (size_t)row * MM;
    const uint4* Cblk = (const uint4*)(d_Cq + (size_t)r0 * MM) + t;
    float f2p = factive ? d_fSu[row] : 0.f;
    // gcomb: 16 threads/col; colc CLAMPED so every lane executes the shfl
    int colc = min(c0 + (t >> 4), MM - 1);
    bool cwrite = (c0 + (t >> 4)) < c1;
    int sub = t & 15;
    unsigned bcnt = 0;

    for (int it = 0; it < N_ITERS; it++) {
        // stage g2 (L2-coherent loads: written by other blocks)
        ((float4*)sg)[t]        = __ldcg(((const float4*)d_g2) + t);
        ((float4*)sg)[t + 1024] = __ldcg(((const float4*)d_g2) + t + 1024);
        __syncthreads();

        // ---- f-pass: warp w owns row r0+w; lane l owns cols seg*128 + l*4..+3
        //      (contiguous 16B per lane -> conflict-free LDS.128, coalesced LDG)
        if (factive) {
            float s0 = 0.f, s1 = 0.f, s2 = 0.f, s3 = 0.f;
            #pragma unroll 8
            for (int seg = 0; seg < 64; seg++) {
                int col = seg * 128 + l * 4;
                uint2 cv = *(const uint2*)(Crow16 + col);
                float4 gv = *(const float4*)(sg + col);
                s0 += ex2(fmaf(qf_lo(cv.x), -K2, gv.x) + f2p);
                s1 += ex2(fmaf(qf_hi(cv.x), -K2, gv.y) + f2p);
                s2 += ex2(fmaf(qf_lo(cv.y), -K2, gv.z) + f2p);
                s3 += ex2(fmaf(qf_hi(cv.y), -K2, gv.w) + f2p);
            }
            float S = (s0 + s1) + (s2 + s3);
            #pragma unroll
            for (int o = 16; o; o >>= 1) S += __shfl_xor_sync(0xffffffffu, S, o);
            S = fmaxf(S, 1e-37f);
            float f = LOGA - LN2F * (lg2(S) - f2p);
            float fle = f * LOG2EF;
            f2p = fle;
            if (l == 0) {
                sf[w] = fle + fgC;
                if (it == N_ITERS - 1) d_f[row] = f;
            }
        }
        __syncthreads();

        // ---- gpart: thread t owns cols t*8..t*8+7 over this block's rows ----
        float a0 = 0.f, a1 = 0.f, a2 = 0.f, a3 = 0.f;
        float a4 = 0.f, a5 = 0.f, a6 = 0.f, a7 = 0.f;
        #pragma unroll 4
        for (int rr = 0; rr < nr; rr++) {
            float FA = sf[rr];
            uint4 cv = Cblk[(size_t)rr * 1024];
            a0 += ex2(fmaf(qf_lo(cv.x), -K2, FA));
            a1 += ex2(fmaf(qf_hi(cv.x), -K2, FA));
            a2 += ex2(fmaf(qf_lo(cv.y), -K2, FA));
            a3 += ex2(fmaf(qf_hi(cv.y), -K2, FA));
            a4 += ex2(fmaf(qf_lo(cv.z), -K2, FA));
            a5 += ex2(fmaf(qf_hi(cv.z), -K2, FA));
            a6 += ex2(fmaf(qf_lo(cv.w), -K2, FA));
            a7 += ex2(fmaf(qf_hi(cv.w), -K2, FA));
        }
        {
            float* dst = d_ps + (size_t)blk * MM + (size_t)t * 8;
            *(float4*)(dst)     = make_float4(a0, a1, a2, a3);
            *(float4*)(dst + 4) = make_float4(a4, a5, a6, a7);
        }
        bcnt += GRID;
        gridbar(t, bcnt);

        // ---- gcomb: block owns cols [c0, c1); all lanes compute (clamped) ----
        {
            float V = 0.f;
            #pragma unroll 5
            for (int k = sub; k < GRID; k += 16)
                V += __ldcg(&d_ps[(size_t)k * MM + colc]);
            #pragma unroll
            for (int o = 8; o; o >>= 1) V += __shfl_xor_sync(0xffffffffu, V, o, 16);
            if (sub == 0 && cwrite) {
                V = fmaxf(V, 1e-37f);
                float g = d_logb[colc] - LN2F * lg2(V);
                d_g2[colc] = fmaf(g, LOG2EF, fgC);
                if (it == N_ITERS - 1) d_g[colc] = g;
            }
        }
        bcnt += GRID;
        gridbar(t, bcnt);
    }
}

// ---------------- final OT loss ----------------
__global__ __launch_bounds__(256) void k_ot() {
    int t = threadIdx.x;
    int j = blockIdx.x * 1024 + t * 4;
    int r0 = blockIdx.y * (NN / CHUNKS);
    float K2 = d_qK2, stepf = d_step, qB = d_qdqB, fgC = d_fgC;
    float4 gv = *(const float4*)(d_g + j);
    float base[4];
    base[0] = fmaf(gv.x, LOG2EF, fgC);
    base[1] = fmaf(gv.y, LOG2EF, fgC);
    base[2] = fmaf(gv.z, LOG2EF, fgC);
    base[3] = fmaf(gv.w, LOG2EF, fgC);
    const unsigned short* Cb = d_Cq + j;
    float acc = 0.f;
    for (int r = r0; r < r0 + (NN / CHUNKS); r++) {
        float frl2 = __ldg(&d_f[r]) * LOG2EF;
        uint2 v = *(const uint2*)(Cb + (size_t)r * MM);
        float qf[4] = {qf_lo(v.x), qf_hi(v.x), qf_lo(v.y), qf_hi(v.y)};
        #pragma unroll
        for (int c = 0; c < 4; c++) {
            float p = ex2(fmaf(qf[c], -K2, base[c] + frl2));
            float cd = fmaf(qf[c], stepf, qB);
            acc = fmaf(p, cd, acc);
        }
    }
    double da = (double)acc;
    #pragma unroll
    for (int o = 16; o; o >>= 1) da += __shfl_down_sync(0xffffffffu, da, o);
    __shared__ double sd[8];
    int lane = t & 31, w = t >> 5;
    if (lane == 0) sd[w] = da;
    __syncthreads();
    if (t == 0) {
        double tot = 0.0;
        #pragma unroll
        for (int k = 0; k < 8; k++) tot += sd[k];
        atomicAdd(&d_ot, tot);
    }
}

// ---------------- supervised alignment MSE ----------------
__global__ __launch_bounds__(128) void k_dist(const float* __restrict__ X,
                                              const float* __restrict__ W,
                                              const int* __restrict__ al) {
    int row = blockIdx.x, t = threadIdx.x;
    long long idx; int mask;
    if (d_is64) {
        long long v = ((const long long*)al)[row];
        mask = (v != -1LL);
        idx = v < 0 ? 0 : v;
    } else {
        int v = al[row];
        mask = (v != -1);
        idx = v < 0 ? 0 : (long long)v;
    }
    float4 a = ((const float4*)X)[(size_t)row * (DD / 4) + t];
    float4 b = ((const float4*)W)[(size_t)idx * (DD / 4) + t];
    float dx = a.x - b.x, dy = a.y - b.y, dz = a.z - b.z, dw = a.w - b.w;
    float s = dx * dx + dy * dy + dz * dz + dw * dw;
    #pragma unroll
    for (int o = 16; o; o >>= 1) s += __shfl_down_sync(0xffffffffu, s, o);
    __shared__ float red[4];
    if ((t & 31) == 0) red[t >> 5] = s;
    __syncthreads();
    if (t == 0) {
        float tot = red[0] + red[1] + red[2] + red[3];
        if (mask) {
            atomicAdd(&d_sq, (double)tot);
            atomicAdd(&d_cnt, 1.0);
        }
    }
}

// ---------------- finalize ----------------
__global__ void k_final(float* out) {
    double dl = (d_cnt > 0.0) ? d_sq / (d_cnt * (double)DD) : 0.0;
    out[0] = (float)(d_ot + dl);
}

// ---------------- launch ----------------
extern "C" void kernel_launch(void* const* d_in, const int* in_sizes, int n_in,
                              void* d_out, int out_size) {
    const float* X  = (const float*)d_in[0];
    const float* W  = (const float*)d_in[1];
    const int*   AL = (const int*)d_in[2];
    const float* T  = (const float*)d_in[3];
    float* out = (float*)d_out;

    k_init<<<1, 1024>>>(T, AL);
    k_sqnorm<<<NN, 128>>>(X, 0);
    k_sqnorm<<<MM, 128>>>(W, 1);
    k_scale<<<1, 1024>>>();
    dim3 gg(MM / 128, NN / 128);
    k_gemm<<<gg, 256>>>(X, W);
    k_ginit<<<MM / 256, 256>>>();

    k_loop<<<GRID, 1024>>>();

    k_ot<<<dim3(8, CHUNKS), 256>>>();
    k_dist<<<NN, 128>>>(X, W, AL);
    k_final<<<1, 1>>>(out);
}